// round 9
// baseline (speedup 1.0000x reference)
#include <cuda_runtime.h>

// reshape_78271484002964: [16,64,256,256] f32, SPLIT=(2,16,16), map_type=1.
// out[b,i,j,k,cc,hh,ww] = in[b,i,cc,j,hh,k,ww]
// sizes: b=16, i=2, j=16, k=16, cc=32, hh=16, ww=16.
//
// float4-unit bit maps (24 bits).
// Input m (fast->slow):  ww4 [0,2) | k [2,6) | hh [6,10) | j [10,14)
//                        | cc [14,19) | i 19 | b [20,24)
// Output g (fast->slow): ww4 [0,2) | hh [2,6) | cc [6,11) | k [11,15)
//                        | j [15,19) | i 19 | b [20,24)
//
// R9: input-order iteration with a LANE REMAP so each warp's store covers
// complete 128 B output lines. Lane bits (tid 0-4) map to:
//   tid[0..3] -> m bits 0-3 (ww4, k[0..1])
//   tid[4]    -> m bit 6    (hh0)
// Warp bits: tid[5..6] -> m bits 4-5 (k[2..3]), tid[7] -> m bit 7 (hh1).
// => warp load  = 2 x 256 B contiguous chunks (1 KB apart)   [sector-dense]
//    warp store = 4 x 128 B FULL lines (out bits {0,1,2}+{11,12} vary)
// 8 float4/thread: q -> m bits 8-10 (hh[2..3], j0);
//   in offset q*256, out offset (q&3)*16 + (q>>2)*32768.

__device__ __forceinline__ unsigned in_to_out(unsigned m) {
    return  (m & 3u)                      // ww4
         | (((m >> 6)  & 15u) << 2)       // hh
         | (((m >> 14) & 31u) << 6)       // cc
         | (((m >> 2)  & 15u) << 11)      // k
         | (((m >> 10) & 15u) << 15)      // j
         |  (m & 0xFFF80000u);            // i, b pass through
}

__global__ void __launch_bounds__(256)
reshape_78271484002964_kernel(const float4* __restrict__ in,
                              float4* __restrict__ out) {
    const unsigned tid = threadIdx.x;

    // tid -> in-block m bits (bijection on 8 bits)
    const unsigned mlocal = (tid & 15u)              // ww4, k[0..1]
                          | (((tid >> 5) & 3u) << 4) // k[2..3]
                          | (((tid >> 4) & 1u) << 6) // hh0  (lane bit!)
                          | (((tid >> 7) & 1u) << 7);// hh1

    const unsigned m0   = blockIdx.x * 2048u + mlocal;
    const unsigned out0 = in_to_out(m0);

    float4 v[8];
#pragma unroll
    for (int q = 0; q < 8; q++)
        v[q] = __ldcs(in + m0 + (unsigned)q * 256u);

#pragma unroll
    for (int q = 0; q < 8; q++)
        __stcs(out + out0 + (unsigned)(q & 3) * 16u
                          + (unsigned)(q >> 2) * 32768u, v[q]);
}

extern "C" void kernel_launch(void* const* d_in, const int* in_sizes, int n_in,
                              void* d_out, int out_size) {
    const float4* in  = (const float4*)d_in[0];
    float4*       out = (float4*)d_out;
    // 16,777,216 float4 / 2048 per block = 8192 blocks
    reshape_78271484002964_kernel<<<8192, 256>>>(in, out);
}

// round 10
// speedup vs baseline: 1.0260x; 1.0260x over previous
#include <cuda_runtime.h>

// reshape_78271484002964: [16,64,256,256] f32, SPLIT=(2,16,16), map_type=1.
// out[b,i,j,k,cc,hh,ww] = in[b,i,cc,j,hh,k,ww]
// sizes: b=16, i=2, j=16, k=16, cc=32, hh=16, ww=16.
//
// float4-unit bit maps (24 bits).
// Input m (fast->slow):  ww4 [0,2) | k [2,6) | hh [6,10) | j [10,14)
//                        | cc [14,19) | i 19 | b [20,24)
// Output g (fast->slow): ww4 [0,2) | hh [2,6) | cc [6,11) | k [11,15)
//                        | j [15,19) | i 19 | b [20,24)
//
// R10: identical structure to the 81.7us best (input-order, 8 float4/thread,
// MLP=8, contiguous warp loads, 64B-granule scattered stores) but with the
// .cs evict-first hints REMOVED. Rationale: evict-first forces eager,
// small-batch L2 writebacks of the scattered store stream; default policy
// lets the 126MB L2 accumulate dirty lines and issue larger writeback bursts
// -> fewer DRAM read/write turnarounds.

__device__ __forceinline__ unsigned in_to_out(unsigned m) {
    return  (m & 3u)                      // ww4
         | (((m >> 6)  & 15u) << 2)       // hh
         | (((m >> 14) & 31u) << 6)       // cc
         | (((m >> 2)  & 15u) << 11)      // k
         | (((m >> 10) & 15u) << 15)      // j
         |  (m & 0xFFF80000u);            // i, b pass through
}

__global__ void __launch_bounds__(256)
reshape_78271484002964_kernel(const float4* __restrict__ in,
                              float4* __restrict__ out) {
    const unsigned m0   = blockIdx.x * 2048u + threadIdx.x;
    const unsigned out0 = in_to_out(m0);

    float4 v[8];
#pragma unroll
    for (int q = 0; q < 8; q++)
        v[q] = in[m0 + (unsigned)q * 256u];

#pragma unroll
    for (int q = 0; q < 8; q++)
        out[out0 + (unsigned)(q & 3) * 16u
                 + (unsigned)(q >> 2) * 32768u] = v[q];
}

extern "C" void kernel_launch(void* const* d_in, const int* in_sizes, int n_in,
                              void* d_out, int out_size) {
    const float4* in  = (const float4*)d_in[0];
    float4*       out = (float4*)d_out;
    // 16,777,216 float4 / 2048 per block = 8192 blocks
    reshape_78271484002964_kernel<<<8192, 256>>>(in, out);
}

// round 11
// speedup vs baseline: 1.0364x; 1.0102x over previous
#include <cuda_runtime.h>

// reshape_78271484002964: [16,64,256,256] f32, SPLIT=(2,16,16), map_type=1.
// out[b,i,j,k,cc,hh,ww] = in[b,i,cc,j,hh,k,ww]
// sizes: b=16, i=2, j=16, k=16, cc=32, hh=16, ww=16.
//
// float4-unit bit maps (24 bits).
// Input m (fast->slow):  ww4 [0,2) | k [2,6) | hh [6,10) | j [10,14)
//                        | cc [14,19) | i 19 | b [20,24)
// Output g (fast->slow): ww4 [0,2) | hh [2,6) | cc [6,11) | k [11,15)
//                        | j [15,19) | i 19 | b [20,24)
//
// R11: input-order iteration, 16 float4 per thread (MLP=16), 4096 blocks
// (half the waves of the 8192-block best). Per-thread q spans m bits 8-11:
//   m8,m9 = hh[2..3] -> out bits 4,5  (stride 16)
//   m10   = j0       -> out bit 15    (stride 32768)
//   m11   = j1       -> out bit 16    (stride 65536)
// Loads: warp = 512 B fully contiguous, stride 1 KiB between q's.
// Stores: 64 B granules, L2-merged (proven fine in R8/R10).

__device__ __forceinline__ unsigned in_to_out(unsigned m) {
    return  (m & 3u)                      // ww4
         | (((m >> 6)  & 15u) << 2)       // hh
         | (((m >> 14) & 31u) << 6)       // cc
         | (((m >> 2)  & 15u) << 11)      // k
         | (((m >> 10) & 15u) << 15)      // j
         |  (m & 0xFFF80000u);            // i, b pass through
}

__global__ void __launch_bounds__(256)
reshape_78271484002964_kernel(const float4* __restrict__ in,
                              float4* __restrict__ out) {
    const unsigned m0   = blockIdx.x * 4096u + threadIdx.x;
    const unsigned out0 = in_to_out(m0);

    float4 v[16];
#pragma unroll
    for (int q = 0; q < 16; q++)
        v[q] = __ldcs(in + m0 + (unsigned)q * 256u);

#pragma unroll
    for (int q = 0; q < 16; q++)
        __stcs(out + out0 + (unsigned)(q & 3) * 16u
                          + (unsigned)((q >> 2) & 1) * 32768u
                          + (unsigned)(q >> 3) * 65536u, v[q]);
}

extern "C" void kernel_launch(void* const* d_in, const int* in_sizes, int n_in,
                              void* d_out, int out_size) {
    const float4* in  = (const float4*)d_in[0];
    float4*       out = (float4*)d_out;
    // 16,777,216 float4 / 4096 per block = 4096 blocks
    reshape_78271484002964_kernel<<<4096, 256>>>(in, out);
}